// round 6
// baseline (speedup 1.0000x reference)
#include <cuda_runtime.h>
#include <math.h>

// Shapes (fixed by problem)
#define B_    256
#define L_    32
#define H_    512
#define NROWS (B_ * L_)      // 8192 slots
#define NCOMP (5 * H_)       // 2560
#define NBLK  320            // persistent loop grid (must all be co-resident)

// ---------------- persistent device state (device-code access ONLY) ------
__device__ float g_h [NROWS * H_];
__device__ float g_c [NROWS * H_];
__device__ float g_nh[NROWS * H_];
__device__ float g_nc[NROWS * H_];
__device__ float g_pl[NROWS * NCOMP];
__device__ float g_pr[NROWS * NCOMP];
__device__ float g_logit[NROWS];
__device__ int   g_idx[B_ * L_];
__device__ int   g_et[NROWS + 31 * 256];
__device__ int4  g_pt[NROWS + 31 * 512];
__device__ int   g_ec[34];
__device__ int   g_pc[34];
__device__ unsigned g_barv;              // grid-barrier counter

__device__ __forceinline__ float sigmf(float x) { return 1.f / (1.f + expf(-x)); }

// ---------------- init ----------------
__global__ void k_zero() {
    if (threadIdx.x < 34) { g_ec[threadIdx.x] = 0; g_pc[threadIdx.x] = 0; }
    if (threadIdx.x == 0) g_barv = 0u;
}

__global__ void k_init(const int* __restrict__ length) {
    int b = blockIdx.x;
    g_idx[b * 32 + threadIdx.x] = threadIdx.x;
    if (threadIdx.x == 0) {
        int len = length[b];
        int be = atomicAdd(&g_ec[32], len);
        for (int e = 0; e < len; e++) g_et[be + e] = b * 32 + e;
        int bp = atomicAdd(&g_pc[32], len - 1);
        for (int k = 0; k < len - 1; k++) g_pt[bp + k] = make_int4(b, k, k + 1, k);
    }
}

// ---------------- gather GEMM (initial phase only), K = 512 --------------
// MODE 0 (word proj): A = X[et], B = Ww (N=1024), +bw, out -> g_h|g_c
// MODE 1 (partials):  A = g_h[et], B = Wc halves (N=5120), out -> g_pl|g_pr
template<int BM, int MODE>
__global__ void k_ggemm(int et_off, int ci,
                        const float* __restrict__ X,
                        const float* __restrict__ W,
                        const float* __restrict__ bias)
{
    constexpr int BN = 64, BK = 16;
    constexpr int TM = BM / 16;
    constexpr int NLA = (BM * BK) / (256 * 4);
    int nt = g_ec[ci];
    int mbase = blockIdx.y * BM;
    if (mbase >= nt) return;
    int nbase = blockIdx.x * BN;
    __shared__ float As[BK][BM + 4];
    __shared__ float Bs[BK][BN + 4];
    int tid = threadIdx.x;
    int tx = tid & 15, ty = tid >> 4;
    float acc[TM][4];
#pragma unroll
    for (int i = 0; i < TM; i++)
#pragma unroll
        for (int j = 0; j < 4; j++) acc[i][j] = 0.f;

    const float* Abase = (MODE == 0) ? X : g_h;
    const float* aptr[NLA];
    int ar[NLA], ak[NLA];
    bool av[NLA];
#pragma unroll
    for (int l = 0; l < NLA; l++) {
        int fa = tid + l * 256;
        ar[l] = fa >> 2; ak[l] = (fa & 3) * 4;
        int m = mbase + ar[l];
        av[l] = (m < nt);
        aptr[l] = av[l] ? (Abase + (size_t)g_et[et_off + m] * 512) : Abase;
    }
    int br = tid >> 2, bk = (tid & 3) * 4;
    int nb = nbase + br;
    const float* wp;
    if (MODE == 0) wp = W + (size_t)nb * 512;
    else           wp = (nb < NCOMP) ? (W + (size_t)nb * 1024)
                                     : (W + (size_t)(nb - NCOMP) * 1024 + 512);

    for (int kt = 0; kt < 512; kt += BK) {
#pragma unroll
        for (int l = 0; l < NLA; l++) {
            float4 a = av[l] ? *(const float4*)(aptr[l] + kt + ak[l])
                             : make_float4(0.f, 0.f, 0.f, 0.f);
            As[ak[l] + 0][ar[l]] = a.x; As[ak[l] + 1][ar[l]] = a.y;
            As[ak[l] + 2][ar[l]] = a.z; As[ak[l] + 3][ar[l]] = a.w;
        }
        float4 bv = *(const float4*)(wp + kt + bk);
        Bs[bk + 0][br] = bv.x; Bs[bk + 1][br] = bv.y;
        Bs[bk + 2][br] = bv.z; Bs[bk + 3][br] = bv.w;
        __syncthreads();
#pragma unroll
        for (int kk = 0; kk < BK; kk++) {
            float a[TM], bb[4];
#pragma unroll
            for (int j = 0; j < TM / 4; j++) {
                float4 t = *(const float4*)&As[kk][ty * TM + 4 * j];
                a[4 * j] = t.x; a[4 * j + 1] = t.y; a[4 * j + 2] = t.z; a[4 * j + 3] = t.w;
            }
            {
                float4 t = *(const float4*)&Bs[kk][tx * 4];
                bb[0] = t.x; bb[1] = t.y; bb[2] = t.z; bb[3] = t.w;
            }
#pragma unroll
            for (int im = 0; im < TM; im++)
#pragma unroll
                for (int in = 0; in < 4; in++) acc[im][in] += a[im] * bb[in];
        }
        __syncthreads();
    }
#pragma unroll
    for (int im = 0; im < TM; im++) {
        int m = mbase + ty * TM + im;
        if (m < nt) {
            int s = g_et[et_off + m];
#pragma unroll
            for (int in = 0; in < 4; in++) {
                int nn = nbase + tx * 4 + in;
                if (MODE == 0) {
                    float val = acc[im][in] + bias[nn];
                    if (nn < 512) g_h[(size_t)s * 512 + nn] = val;
                    else          g_c[(size_t)s * 512 + nn - 512] = val;
                } else {
                    float val = acc[im][in];
                    if (nn < NCOMP) g_pl[(size_t)s * NCOMP + nn] = val;
                    else            g_pr[(size_t)s * NCOMP + nn - NCOMP] = val;
                }
            }
        }
    }
}

// ---------------- initial pair elementwise (standalone) ------------------
__global__ void k_ew(int pt_off, int ci,
                     const float* __restrict__ bc, const float* __restrict__ q) {
    int t = blockIdx.x;
    if (t >= g_pc[ci]) return;
    int4 tk = g_pt[pt_off + t];
    int b = tk.x, sl = tk.y, sr = tk.z, dst = tk.w;
    int e = threadIdx.x;
    const float4* pl  = (const float4*)(g_pl + (size_t)(b * 32 + sl) * NCOMP);
    const float4* pr  = (const float4*)(g_pr + (size_t)(b * 32 + sr) * NCOMP);
    const float4* bc4 = (const float4*)bc;
    const float4* cl4 = (const float4*)(g_c + (size_t)(b * 32 + sl) * H_);
    const float4* cr4 = (const float4*)(g_c + (size_t)(b * 32 + sr) * H_);
    float4* nh4 = (float4*)(g_nh + (size_t)(b * 32 + dst) * H_);
    float4* nc4 = (float4*)(g_nc + (size_t)(b * 32 + dst) * H_);
    const float4* q4 = (const float4*)q;

    float4 vi, vfl, vfr, vu, vo;
#define G(dst_, g_) { float4 a = pl[(g_)*128 + e]; float4 bq = pr[(g_)*128 + e]; float4 c = bc4[(g_)*128 + e]; \
    dst_.x = a.x + bq.x + c.x; dst_.y = a.y + bq.y + c.y; dst_.z = a.z + bq.z + c.z; dst_.w = a.w + bq.w + c.w; }
    G(vi, 0) G(vfl, 1) G(vfr, 2) G(vu, 3) G(vo, 4)
#undef G
    float4 cl = cl4[e], cr = cr4[e];
    float4 cn, hn;
#define C1(m) cn.m = cl.m * sigmf(vfl.m + 1.f) + cr.m * sigmf(vfr.m + 1.f) + tanhf(vu.m) * sigmf(vi.m); \
              hn.m = sigmf(vo.m) * tanhf(cn.m);
    C1(x) C1(y) C1(z) C1(w)
#undef C1
    nh4[e] = hn; nc4[e] = cn;
    float4 qv = q4[e];
    float accq = qv.x * hn.x + qv.y * hn.y + qv.z * hn.z + qv.w * hn.w;
    for (int o = 16; o > 0; o >>= 1) accq += __shfl_down_sync(0xffffffffu, accq, o);
    __shared__ float red[4];
    if ((threadIdx.x & 31) == 0) red[threadIdx.x >> 5] = accq;
    __syncthreads();
    if (threadIdx.x == 0) {
        float s = red[0] + red[1] + red[2] + red[3];
        g_logit[b * 32 + dst] = s * 0.04419417382415922f;
    }
}

// ---------------- persistent fused loop ----------------------------------
__device__ __forceinline__ void gbar(unsigned &target) {
    __syncthreads();
    if (threadIdx.x == 0) {
        __threadfence();
        atomicAdd(&g_barv, 1u);
        target += NBLK;
        while (*((volatile unsigned*)&g_barv) < target) { }
        __threadfence();
    }
    __syncthreads();
}

__global__ __launch_bounds__(256, 3)
void k_loop(const int* __restrict__ length, const float* __restrict__ Wc,
            const float* __restrict__ bc, const float* __restrict__ q) {
    int bid = blockIdx.x, tid = threadIdx.x;
    unsigned target = 0;
    __shared__ float As[16][64 + 4];
    __shared__ float Bs[16][64 + 4];
    __shared__ float redc[2][4];
    __shared__ int s_sl;

    for (int step = 0; step < 31; step++) {
        // ---- Phase A: select + commit (blocks 0..255, one batch each) ----
        if (bid < B_) {
            int b = bid;
            if (tid == 0) {
                int len = length[b];
                int vc = len - step - 1;
                int sl = -1;
                if (vc >= 1) {
                    int n = 32 - step;
                    int* ip = g_idx + b * 32;
                    float best = -3.0e38f; int jb = 0;
                    for (int k = 0; k < vc; k++) {
                        float lg = g_logit[b * 32 + ip[k]];
                        if (lg > best) { best = lg; jb = k; }
                    }
                    sl = ip[jb];
                    if (step < 30) {
                        int nt2 = 0; int4 tk[2];
                        if (jb >= 1)      tk[nt2++] = make_int4(b, ip[jb - 1], sl, ip[jb - 1]);
                        if (jb <= vc - 2) tk[nt2++] = make_int4(b, sl, ip[jb + 2], sl);
                        if (nt2) {
                            int base = atomicAdd(&g_pc[step], nt2);
                            for (int t = 0; t < nt2; t++) g_pt[8192 + step * 512 + base + t] = tk[t];
                            int eb = atomicAdd(&g_ec[step], 1);
                            g_et[8192 + step * 256 + eb] = b * 32 + sl;
                        }
                    }
                    for (int k = jb + 1; k < n - 1; k++) ip[k] = ip[k + 1];
                }
                s_sl = sl;
            }
            __syncthreads();
            int sl = s_sl;
            if (sl >= 0) {
                size_t ro = (size_t)(b * 32 + sl) * H_;
                int e = tid & 127;
                if (tid < 128) ((float4*)(g_h + ro))[e] = ((const float4*)(g_nh + ro))[e];
                else           ((float4*)(g_c + ro))[e] = ((const float4*)(g_nc + ro))[e];
            }
        }
        gbar(target);
        if (step == 30) break;

        // ---- Phase B: partial GEMM, 320 tiles == 320 blocks --------------
        {
            int nt = g_ec[step];
            int mbase = (bid & 3) * 64;
            int nbase = (bid >> 2) * 64;
            if (mbase < nt) {
                int tx = tid & 15, ty = tid >> 4;
                float acc[4][4];
#pragma unroll
                for (int i = 0; i < 4; i++)
#pragma unroll
                    for (int j = 0; j < 4; j++) acc[i][j] = 0.f;
                int ar = tid >> 2, ak = (tid & 3) * 4;
                int m = mbase + ar;
                bool av = m < nt;
                const float* aptr = av ? (g_h + (size_t)g_et[8192 + step * 256 + m] * 512) : g_h;
                int br = tid >> 2, bk = (tid & 3) * 4;
                int nb = nbase + br;
                const float* wp = (nb < NCOMP) ? (Wc + (size_t)nb * 1024)
                                               : (Wc + (size_t)(nb - NCOMP) * 1024 + 512);
                for (int kt = 0; kt < 512; kt += 16) {
                    float4 a = av ? *(const float4*)(aptr + kt + ak)
                                  : make_float4(0.f, 0.f, 0.f, 0.f);
                    As[ak + 0][ar] = a.x; As[ak + 1][ar] = a.y;
                    As[ak + 2][ar] = a.z; As[ak + 3][ar] = a.w;
                    float4 bv = *(const float4*)(wp + kt + bk);
                    Bs[bk + 0][br] = bv.x; Bs[bk + 1][br] = bv.y;
                    Bs[bk + 2][br] = bv.z; Bs[bk + 3][br] = bv.w;
                    __syncthreads();
#pragma unroll
                    for (int kk = 0; kk < 16; kk++) {
                        float4 t0 = *(const float4*)&As[kk][ty * 4];
                        float4 t1 = *(const float4*)&Bs[kk][tx * 4];
                        float aa[4] = {t0.x, t0.y, t0.z, t0.w};
                        float bb[4] = {t1.x, t1.y, t1.z, t1.w};
#pragma unroll
                        for (int im = 0; im < 4; im++)
#pragma unroll
                            for (int in = 0; in < 4; in++) acc[im][in] += aa[im] * bb[in];
                    }
                    __syncthreads();
                }
#pragma unroll
                for (int im = 0; im < 4; im++) {
                    int mm = mbase + ty * 4 + im;
                    if (mm < nt) {
                        int s = g_et[8192 + step * 256 + mm];
#pragma unroll
                        for (int in = 0; in < 4; in++) {
                            int nn = nbase + tx * 4 + in;
                            if (nn < NCOMP) g_pl[(size_t)s * NCOMP + nn] = acc[im][in];
                            else            g_pr[(size_t)s * NCOMP + nn - NCOMP] = acc[im][in];
                        }
                    }
                }
            }
        }
        gbar(target);

        // ---- Phase C: pair elementwise, 2 tasks per block ----------------
        {
            int npairs = g_pc[step];
            int sub = tid >> 7, lt = tid & 127;
            int wig = (tid >> 5) & 3;
            int t = bid * 2 + sub;
            bool valid = (t < npairs);
            float accq = 0.f;
            int bdst = 0;
            if (valid) {
                int4 tk = g_pt[8192 + step * 512 + t];
                int b = tk.x, sl = tk.y, sr = tk.z, dst = tk.w;
                bdst = b * 32 + dst;
                const float4* pl  = (const float4*)(g_pl + (size_t)(b * 32 + sl) * NCOMP);
                const float4* pr  = (const float4*)(g_pr + (size_t)(b * 32 + sr) * NCOMP);
                const float4* bc4 = (const float4*)bc;
                const float4* cl4 = (const float4*)(g_c + (size_t)(b * 32 + sl) * H_);
                const float4* cr4 = (const float4*)(g_c + (size_t)(b * 32 + sr) * H_);
                float4* nh4 = (float4*)(g_nh + (size_t)bdst * H_);
                float4* nc4 = (float4*)(g_nc + (size_t)bdst * H_);
                const float4* q4 = (const float4*)q;
                float4 vi, vfl, vfr, vu, vo;
#define G(dst_, g_) { float4 a = pl[(g_)*128 + lt]; float4 bq = pr[(g_)*128 + lt]; float4 c = bc4[(g_)*128 + lt]; \
    dst_.x = a.x + bq.x + c.x; dst_.y = a.y + bq.y + c.y; dst_.z = a.z + bq.z + c.z; dst_.w = a.w + bq.w + c.w; }
                G(vi, 0) G(vfl, 1) G(vfr, 2) G(vu, 3) G(vo, 4)
#undef G
                float4 cl = cl4[lt], cr = cr4[lt];
                float4 cn, hn;
#define C1(m) cn.m = cl.m * sigmf(vfl.m + 1.f) + cr.m * sigmf(vfr.m + 1.f) + tanhf(vu.m) * sigmf(vi.m); \
              hn.m = sigmf(vo.m) * tanhf(cn.m);
                C1(x) C1(y) C1(z) C1(w)
#undef C1
                nh4[lt] = hn; nc4[lt] = cn;
                float4 qv = q4[lt];
                accq = qv.x * hn.x + qv.y * hn.y + qv.z * hn.z + qv.w * hn.w;
            }
            for (int o = 16; o > 0; o >>= 1) accq += __shfl_down_sync(0xffffffffu, accq, o);
            if ((tid & 31) == 0) redc[sub][wig] = accq;
            __syncthreads();
            if (valid && lt == 0) {
                float s = redc[sub][0] + redc[sub][1] + redc[sub][2] + redc[sub][3];
                g_logit[bdst] = s * 0.04419417382415922f;
            }
        }
        gbar(target);
    }
}

__global__ void k_final(float* __restrict__ out) {
    int b = blockIdx.x;
    ((float4*)out)[b * 128 + threadIdx.x] =
        ((const float4*)(g_h + (size_t)b * 32 * H_))[threadIdx.x];
}

// ---------------- launch ----------------
extern "C" void kernel_launch(void* const* d_in, const int* in_sizes, int n_in,
                              void* d_out, int out_size) {
    const float* x      = (const float*)d_in[0];
    const int*   length = (const int*)  d_in[1];
    const float* Ww     = (const float*)d_in[2];
    const float* bw     = (const float*)d_in[3];
    const float* Wc     = (const float*)d_in[4];
    const float* bc     = (const float*)d_in[5];
    const float* q      = (const float*)d_in[6];
    float* out = (float*)d_out;

    k_zero<<<1, 64>>>();
    k_init<<<B_, 32>>>(length);

    // word projection (gathered, valid elements only)
    k_ggemm<128, 0><<<dim3(1024 / 64, 64), 256>>>(0, 32, x, Ww, bw);
    // initial partial fill
    k_ggemm<128, 1><<<dim3(NCOMP * 2 / 64, 64), 256>>>(0, 32, (const float*)0, Wc, (const float*)0);
    // initial pair cache
    k_ew<<<8192, 128>>>(0, 32, bc, q);

    // fused 30-step loop (single persistent kernel)
    k_loop<<<NBLK, 256>>>(length, Wc, bc, q);

    k_final<<<B_, 128>>>(out);
}

// round 7
// speedup vs baseline: 1.1403x; 1.1403x over previous
#include <cuda_runtime.h>
#include <math.h>

// Shapes (fixed by problem)
#define B_    256
#define L_    32
#define H_    512
#define NROWS (B_ * L_)      // 8192 slots
#define NCOMP (5 * H_)       // 2560

// ---------------- persistent device state (device-code access ONLY) ------
__device__ float g_h [NROWS * H_];
__device__ float g_c [NROWS * H_];
__device__ float g_nh[NROWS * H_];
__device__ float g_nc[NROWS * H_];
__device__ float g_pl[NROWS * NCOMP];
__device__ float g_pr[NROWS * NCOMP];
__device__ float g_logit[NROWS];
__device__ int   g_idx[B_ * L_];
__device__ int   g_et[NROWS];            // initial element-task list (compacted)
__device__ int4  g_pt[NROWS];            // initial pair-task list (compacted)
__device__ int   g_ec[2];                // [0] = initial element count
__device__ int   g_pc[2];                // [0] = initial pair count
__device__ int   g_emerge[B_];           // per-batch merged slot this step (-1 none)
__device__ int   g_ptn[B_];              // per-batch pair-task count (<=2)
__device__ int4  g_ptask[B_ * 2];        // per-batch pair tasks

__device__ __forceinline__ float sigmf(float x) { return 1.f / (1.f + expf(-x)); }

// ---------------- init ----------------
__global__ void k_zero() {
    if (threadIdx.x < 2) { g_ec[threadIdx.x] = 0; g_pc[threadIdx.x] = 0; }
}

__global__ void k_init(const int* __restrict__ length) {
    int b = blockIdx.x;
    g_idx[b * 32 + threadIdx.x] = threadIdx.x;
    if (threadIdx.x == 0) {
        int len = length[b];
        int be = atomicAdd(&g_ec[0], len);
        for (int e = 0; e < len; e++) g_et[be + e] = b * 32 + e;
        int bp = atomicAdd(&g_pc[0], len - 1);
        for (int k = 0; k < len - 1; k++) g_pt[bp + k] = make_int4(b, k, k + 1, k);
    }
}

// ---------------- GEMM, BN=128, BK=16, 256 threads, TMx8 micro-tile -------
// MODE 0 (word proj, et list): A = X[et], B = Ww (N=1024), +bw -> g_h|g_c
// MODE 1 (fill partials, et list): A = g_h[et], B = Wc halves (N=5120) -> g_pl|g_pr
// MODE 2 (step partials, g_emerge): row m = batch m, slot = g_emerge[m]
template<int BM, int MODE>
__global__ void k_gg2(const float* __restrict__ X,
                      const float* __restrict__ W,
                      const float* __restrict__ bias)
{
    constexpr int BN = 128, BK = 16;
    constexpr int TM  = BM / 16;                 // 8 or 4
    constexpr int NLA = (BM * BK) / (256 * 4);   // 2 or 1
    int nt = (MODE == 2) ? B_ : g_ec[0];
    int mbase = blockIdx.y * BM;
    if (mbase >= nt) return;
    int nbase = blockIdx.x * BN;
    __shared__ float As[BK][BM + 4];
    __shared__ float Bs[BK][BN + 4];
    int tid = threadIdx.x;
    int tx = tid & 15, ty = tid >> 4;
    float acc[TM][8];
#pragma unroll
    for (int i = 0; i < TM; i++)
#pragma unroll
        for (int j = 0; j < 8; j++) acc[i][j] = 0.f;

    // A gather pointers
    const float* aptr[NLA];
    int ar[NLA], ak[NLA];
    bool av[NLA];
#pragma unroll
    for (int l = 0; l < NLA; l++) {
        int fa = tid + l * 256;
        ar[l] = fa >> 2; ak[l] = (fa & 3) * 4;
        int m = mbase + ar[l];
        if (MODE == 2) {
            int slot = (m < B_) ? g_emerge[m] : -1;
            av[l] = (slot >= 0);
            aptr[l] = av[l] ? (g_h + (size_t)slot * 512) : g_h;
        } else {
            av[l] = (m < nt);
            const float* base = (MODE == 0) ? X : g_h;
            aptr[l] = av[l] ? (base + (size_t)g_et[m] * 512) : base;
        }
    }
    // B pointers (2 float4 loads/thread)
    int brr[2], bkk[2];
    const float* wp[2];
#pragma unroll
    for (int l = 0; l < 2; l++) {
        int fb = tid + l * 256;
        brr[l] = fb >> 2; bkk[l] = (fb & 3) * 4;
        int nb = nbase + brr[l];
        if (MODE == 0) wp[l] = W + (size_t)nb * 512;
        else           wp[l] = (nb < NCOMP) ? (W + (size_t)nb * 1024)
                                            : (W + (size_t)(nb - NCOMP) * 1024 + 512);
    }

    for (int kt = 0; kt < 512; kt += BK) {
#pragma unroll
        for (int l = 0; l < NLA; l++) {
            float4 a = av[l] ? *(const float4*)(aptr[l] + kt + ak[l])
                             : make_float4(0.f, 0.f, 0.f, 0.f);
            As[ak[l] + 0][ar[l]] = a.x; As[ak[l] + 1][ar[l]] = a.y;
            As[ak[l] + 2][ar[l]] = a.z; As[ak[l] + 3][ar[l]] = a.w;
        }
#pragma unroll
        for (int l = 0; l < 2; l++) {
            float4 bv = *(const float4*)(wp[l] + kt + bkk[l]);
            Bs[bkk[l] + 0][brr[l]] = bv.x; Bs[bkk[l] + 1][brr[l]] = bv.y;
            Bs[bkk[l] + 2][brr[l]] = bv.z; Bs[bkk[l] + 3][brr[l]] = bv.w;
        }
        __syncthreads();
#pragma unroll
        for (int kk = 0; kk < BK; kk++) {
            float a[TM], bb[8];
#pragma unroll
            for (int j = 0; j < TM / 4; j++) {
                float4 t = *(const float4*)&As[kk][ty * TM + 4 * j];
                a[4 * j] = t.x; a[4 * j + 1] = t.y; a[4 * j + 2] = t.z; a[4 * j + 3] = t.w;
            }
            {
                float4 u0 = *(const float4*)&Bs[kk][tx * 8];
                float4 u1 = *(const float4*)&Bs[kk][tx * 8 + 4];
                bb[0] = u0.x; bb[1] = u0.y; bb[2] = u0.z; bb[3] = u0.w;
                bb[4] = u1.x; bb[5] = u1.y; bb[6] = u1.z; bb[7] = u1.w;
            }
#pragma unroll
            for (int im = 0; im < TM; im++)
#pragma unroll
                for (int in = 0; in < 8; in++) acc[im][in] += a[im] * bb[in];
        }
        __syncthreads();
    }
#pragma unroll
    for (int im = 0; im < TM; im++) {
        int m = mbase + ty * TM + im;
        int slot;
        bool ok;
        if (MODE == 2) { slot = (m < B_) ? g_emerge[m] : -1; ok = (slot >= 0); }
        else           { ok = (m < nt); slot = ok ? g_et[m] : 0; }
        if (ok) {
#pragma unroll
            for (int in = 0; in < 8; in++) {
                int nn = nbase + tx * 8 + in;
                if (MODE == 0) {
                    float val = acc[im][in] + bias[nn];
                    if (nn < 512) g_h[(size_t)slot * 512 + nn] = val;
                    else          g_c[(size_t)slot * 512 + nn - 512] = val;
                } else {
                    float val = acc[im][in];
                    if (nn < NCOMP) g_pl[(size_t)slot * NCOMP + nn] = val;
                    else            g_pr[(size_t)slot * NCOMP + nn - NCOMP] = val;
                }
            }
        }
    }
}

// ---------------- initial pair elementwise (compacted list) --------------
__global__ void k_ew(const float* __restrict__ bc, const float* __restrict__ q) {
    int t = blockIdx.x;
    if (t >= g_pc[0]) return;
    int4 tk = g_pt[t];
    int b = tk.x, sl = tk.y, sr = tk.z, dst = tk.w;
    int e = threadIdx.x;
    const float4* pl  = (const float4*)(g_pl + (size_t)(b * 32 + sl) * NCOMP);
    const float4* pr  = (const float4*)(g_pr + (size_t)(b * 32 + sr) * NCOMP);
    const float4* bc4 = (const float4*)bc;
    const float4* cl4 = (const float4*)(g_c + (size_t)(b * 32 + sl) * H_);
    const float4* cr4 = (const float4*)(g_c + (size_t)(b * 32 + sr) * H_);
    float4* nh4 = (float4*)(g_nh + (size_t)(b * 32 + dst) * H_);
    float4* nc4 = (float4*)(g_nc + (size_t)(b * 32 + dst) * H_);
    const float4* q4 = (const float4*)q;

    float4 vi, vfl, vfr, vu, vo;
#define G(dst_, g_) { float4 a = pl[(g_)*128 + e]; float4 bq = pr[(g_)*128 + e]; float4 c = bc4[(g_)*128 + e]; \
    dst_.x = a.x + bq.x + c.x; dst_.y = a.y + bq.y + c.y; dst_.z = a.z + bq.z + c.z; dst_.w = a.w + bq.w + c.w; }
    G(vi, 0) G(vfl, 1) G(vfr, 2) G(vu, 3) G(vo, 4)
#undef G
    float4 cl = cl4[e], cr = cr4[e];
    float4 cn, hn;
#define C1(m) cn.m = cl.m * sigmf(vfl.m + 1.f) + cr.m * sigmf(vfr.m + 1.f) + tanhf(vu.m) * sigmf(vi.m); \
              hn.m = sigmf(vo.m) * tanhf(cn.m);
    C1(x) C1(y) C1(z) C1(w)
#undef C1
    nh4[e] = hn; nc4[e] = cn;
    float4 qv = q4[e];
    float accq = qv.x * hn.x + qv.y * hn.y + qv.z * hn.z + qv.w * hn.w;
    for (int o = 16; o > 0; o >>= 1) accq += __shfl_down_sync(0xffffffffu, accq, o);
    __shared__ float red[4];
    if ((threadIdx.x & 31) == 0) red[threadIdx.x >> 5] = accq;
    __syncthreads();
    if (threadIdx.x == 0) {
        float s = red[0] + red[1] + red[2] + red[3];
        g_logit[b * 32 + dst] = s * 0.04419417382415922f;
    }
}

// ---------------- fused: ew(step-1 tasks) + select(step) + commit --------
__global__ void k_fused(const int* __restrict__ length,
                        const float* __restrict__ bc, const float* __restrict__ q,
                        int step) {
    int b = blockIdx.x, tid = threadIdx.x;
    __shared__ float redc[2][4];
    __shared__ int s_sl;

    if (step > 0) {
        int ntask = g_ptn[b];
        int sub = tid >> 7, lt = tid & 127;
        int wig = (tid >> 5) & 3;
        bool valid = (sub < ntask);
        float accq = 0.f;
        int bdst = 0;
        if (valid) {
            int4 tk = g_ptask[b * 2 + sub];
            int sl = tk.y, sr = tk.z, dst = tk.w;
            bdst = b * 32 + dst;
            const float4* pl  = (const float4*)(g_pl + (size_t)(b * 32 + sl) * NCOMP);
            const float4* pr  = (const float4*)(g_pr + (size_t)(b * 32 + sr) * NCOMP);
            const float4* bc4 = (const float4*)bc;
            const float4* cl4 = (const float4*)(g_c + (size_t)(b * 32 + sl) * H_);
            const float4* cr4 = (const float4*)(g_c + (size_t)(b * 32 + sr) * H_);
            float4* nh4 = (float4*)(g_nh + (size_t)bdst * H_);
            float4* nc4 = (float4*)(g_nc + (size_t)bdst * H_);
            const float4* q4 = (const float4*)q;
            float4 vi, vfl, vfr, vu, vo;
#define G(dst_, g_) { float4 a = pl[(g_)*128 + lt]; float4 bq = pr[(g_)*128 + lt]; float4 c = bc4[(g_)*128 + lt]; \
    dst_.x = a.x + bq.x + c.x; dst_.y = a.y + bq.y + c.y; dst_.z = a.z + bq.z + c.z; dst_.w = a.w + bq.w + c.w; }
            G(vi, 0) G(vfl, 1) G(vfr, 2) G(vu, 3) G(vo, 4)
#undef G
            float4 cl = cl4[lt], cr = cr4[lt];
            float4 cn, hn;
#define C1(m) cn.m = cl.m * sigmf(vfl.m + 1.f) + cr.m * sigmf(vfr.m + 1.f) + tanhf(vu.m) * sigmf(vi.m); \
              hn.m = sigmf(vo.m) * tanhf(cn.m);
            C1(x) C1(y) C1(z) C1(w)
#undef C1
            nh4[lt] = hn; nc4[lt] = cn;
            float4 qv = q4[lt];
            accq = qv.x * hn.x + qv.y * hn.y + qv.z * hn.z + qv.w * hn.w;
        }
        for (int o = 16; o > 0; o >>= 1) accq += __shfl_down_sync(0xffffffffu, accq, o);
        if ((tid & 31) == 0) redc[sub][wig] = accq;
        __syncthreads();
        if (valid && lt == 0) {
            float s = redc[sub][0] + redc[sub][1] + redc[sub][2] + redc[sub][3];
            g_logit[bdst] = s * 0.04419417382415922f;
        }
        __syncthreads();
    }

    // select + task emit (per-batch slots, no atomics)
    if (tid == 0) {
        int len = length[b];
        int vc = len - step - 1;
        int sl = -1, nt2 = 0;
        if (vc >= 1) {
            int n = 32 - step;
            int* ip = g_idx + b * 32;
            float best = -3.0e38f; int jb = 0;
            for (int k = 0; k < vc; k++) {     // first-max tie-break == jnp.argmax
                float lg = g_logit[b * 32 + ip[k]];
                if (lg > best) { best = lg; jb = k; }
            }
            sl = ip[jb];
            if (step < 30) {
                if (jb >= 1)      g_ptask[b * 2 + nt2++] = make_int4(b, ip[jb - 1], sl, ip[jb - 1]);
                if (jb <= vc - 2) g_ptask[b * 2 + nt2++] = make_int4(b, sl, ip[jb + 2], sl);
            }
            for (int k = jb + 1; k < n - 1; k++) ip[k] = ip[k + 1];
        }
        g_ptn[b] = nt2;
        g_emerge[b] = (sl >= 0 && step < 30) ? (b * 32 + sl) : -1;
        s_sl = sl;
    }
    __syncthreads();
    int sl = s_sl;
    if (sl >= 0) {   // commit merge: cached compose -> live h/c
        size_t ro = (size_t)(b * 32 + sl) * H_;
        int e = tid & 127;
        if (tid < 128) ((float4*)(g_h + ro))[e] = ((const float4*)(g_nh + ro))[e];
        else           ((float4*)(g_c + ro))[e] = ((const float4*)(g_nc + ro))[e];
    }
}

__global__ void k_final(float* __restrict__ out) {
    int b = blockIdx.x;   // element 0 lives in slot 0 forever
    ((float4*)out)[b * 128 + threadIdx.x] =
        ((const float4*)(g_h + (size_t)b * 32 * H_))[threadIdx.x];
}

// ---------------- launch ----------------
extern "C" void kernel_launch(void* const* d_in, const int* in_sizes, int n_in,
                              void* d_out, int out_size) {
    const float* x      = (const float*)d_in[0];
    const int*   length = (const int*)  d_in[1];
    const float* Ww     = (const float*)d_in[2];
    const float* bw     = (const float*)d_in[3];
    const float* Wc     = (const float*)d_in[4];
    const float* bc     = (const float*)d_in[5];
    const float* q      = (const float*)d_in[6];
    float* out = (float*)d_out;

    k_zero<<<1, 32>>>();
    k_init<<<B_, 32>>>(length);

    // word projection (gathered, valid elements only): h|c = x @ Ww^T + bw
    k_gg2<128, 0><<<dim3(1024 / 128, 64), 256>>>(x, Ww, bw);
    // initial partial fill: pl|pr = Wl@h | Wr@h for all valid elements
    k_gg2<128, 1><<<dim3(5120 / 128, 64), 256>>>((const float*)0, Wc, (const float*)0);
    // initial pair cache (adds + activations + logits)
    k_ew<<<8192, 128>>>(bc, q);

    for (int i = 0; i < 31; i++) {
        k_fused<<<B_, 256>>>(length, bc, q, i);
        if (i < 30)
            k_gg2<64, 2><<<dim3(5120 / 128, 4), 256>>>((const float*)0, Wc, (const float*)0);
    }
    k_final<<<B_, 128>>>(out);
}

// round 8
// speedup vs baseline: 1.7315x; 1.5184x over previous
#include <cuda_runtime.h>
#include <math.h>

// Shapes (fixed by problem)
#define B_    256
#define L_    32
#define H_    512
#define NROWS (B_ * L_)      // 8192 slots
#define NCOMP (5 * H_)       // 2560

// ---------------- persistent device state (device-code access ONLY) ------
__device__ float g_h [NROWS * H_];
__device__ float g_c [NROWS * H_];
__device__ float g_nh[NROWS * H_];
__device__ float g_nc[NROWS * H_];
__device__ float g_pl[NROWS * NCOMP];
__device__ float g_pr[NROWS * NCOMP];
__device__ float g_logit[NROWS];
__device__ int   g_idx[B_ * L_];
__device__ int   g_et[NROWS];            // initial element-task list (compacted)
__device__ int4  g_pt[NROWS];            // initial pair-task list (compacted)
__device__ int   g_ec[2];                // [0] = initial element count
__device__ int   g_pc[2];                // [0] = initial pair count
__device__ int   g_perm[B_];             // batches sorted by length desc (stable)
__device__ int   g_nact[32];             // #batches merging at step i
__device__ int   g_emerge[B_];           // per-batch merged slot this step (-1 none)
__device__ int   g_ptn[B_];              // per-batch pair-task count (<=2)
__device__ int4  g_ptask[B_ * 2];        // per-batch pair tasks

__device__ __forceinline__ float sigmf(float x) { return 1.f / (1.f + expf(-x)); }

// ---------------- init ----------------
__global__ void k_zero() {
    if (threadIdx.x < 2) { g_ec[threadIdx.x] = 0; g_pc[threadIdx.x] = 0; }
}

__global__ void k_init(const int* __restrict__ length) {
    int b = blockIdx.x;
    g_idx[b * 32 + threadIdx.x] = threadIdx.x;
    if (threadIdx.x == 0) {
        int len = length[b];
        int be = atomicAdd(&g_ec[0], len);
        for (int e = 0; e < len; e++) g_et[be + e] = b * 32 + e;
        int bp = atomicAdd(&g_pc[0], len - 1);
        for (int k = 0; k < len - 1; k++) g_pt[bp + k] = make_int4(b, k, k + 1, k);
    }
}

// length-sorted permutation + per-step active count
__global__ void k_init2(const int* __restrict__ length) {
    __shared__ int slen[B_];
    int t = threadIdx.x;
    slen[t] = length[t];
    __syncthreads();
    int myl = slen[t];
    int rank = 0;
    for (int j = 0; j < B_; j++) {
        int lj = slen[j];
        if (lj > myl || (lj == myl && j < t)) rank++;
    }
    g_perm[rank] = t;
    if (t < 31) {            // batch merges at step i iff len >= i+2
        int cnt = 0;
        for (int j = 0; j < B_; j++) if (slen[j] >= t + 2) cnt++;
        g_nact[t] = cnt;
    }
}

// ---------------- initial gather GEMMs (round-5 proven shape) ------------
// MODE 0 (word proj): A = X[et], B = Ww (N=1024), +bw -> g_h|g_c
// MODE 1 (fill partials): A = g_h[et], B = Wc halves (N=5120) -> g_pl|g_pr
template<int MODE>
__global__ void k_ggemm(const float* __restrict__ X,
                        const float* __restrict__ W,
                        const float* __restrict__ bias)
{
    constexpr int BM = 128, BN = 64, BK = 16;
    int nt = g_ec[0];
    int mbase = blockIdx.y * BM;
    if (mbase >= nt) return;
    int nbase = blockIdx.x * BN;
    __shared__ float As[BK][BM + 4];
    __shared__ float Bs[BK][BN + 4];
    int tid = threadIdx.x;
    int tx = tid & 15, ty = tid >> 4;
    float acc[8][4];
#pragma unroll
    for (int i = 0; i < 8; i++)
#pragma unroll
        for (int j = 0; j < 4; j++) acc[i][j] = 0.f;

    const float* Abase = (MODE == 0) ? X : g_h;
    const float* aptr[2];
    int ar[2], ak[2];
    bool av[2];
#pragma unroll
    for (int l = 0; l < 2; l++) {
        int fa = tid + l * 256;
        ar[l] = fa >> 2; ak[l] = (fa & 3) * 4;
        int m = mbase + ar[l];
        av[l] = (m < nt);
        aptr[l] = av[l] ? (Abase + (size_t)g_et[m] * 512) : Abase;
    }
    int br = tid >> 2, bk = (tid & 3) * 4;
    int nb = nbase + br;
    const float* wp;
    if (MODE == 0) wp = W + (size_t)nb * 512;
    else           wp = (nb < NCOMP) ? (W + (size_t)nb * 1024)
                                     : (W + (size_t)(nb - NCOMP) * 1024 + 512);

    for (int kt = 0; kt < 512; kt += BK) {
#pragma unroll
        for (int l = 0; l < 2; l++) {
            float4 a = av[l] ? *(const float4*)(aptr[l] + kt + ak[l])
                             : make_float4(0.f, 0.f, 0.f, 0.f);
            As[ak[l] + 0][ar[l]] = a.x; As[ak[l] + 1][ar[l]] = a.y;
            As[ak[l] + 2][ar[l]] = a.z; As[ak[l] + 3][ar[l]] = a.w;
        }
        float4 bv = *(const float4*)(wp + kt + bk);
        Bs[bk + 0][br] = bv.x; Bs[bk + 1][br] = bv.y;
        Bs[bk + 2][br] = bv.z; Bs[bk + 3][br] = bv.w;
        __syncthreads();
#pragma unroll
        for (int kk = 0; kk < BK; kk++) {
            float a[8], bb[4];
            {
                float4 t0 = *(const float4*)&As[kk][ty * 8];
                float4 t1 = *(const float4*)&As[kk][ty * 8 + 4];
                a[0] = t0.x; a[1] = t0.y; a[2] = t0.z; a[3] = t0.w;
                a[4] = t1.x; a[5] = t1.y; a[6] = t1.z; a[7] = t1.w;
            }
            {
                float4 t = *(const float4*)&Bs[kk][tx * 4];
                bb[0] = t.x; bb[1] = t.y; bb[2] = t.z; bb[3] = t.w;
            }
#pragma unroll
            for (int im = 0; im < 8; im++)
#pragma unroll
                for (int in = 0; in < 4; in++) acc[im][in] += a[im] * bb[in];
        }
        __syncthreads();
    }
#pragma unroll
    for (int im = 0; im < 8; im++) {
        int m = mbase + ty * 8 + im;
        if (m < nt) {
            int s = g_et[m];
#pragma unroll
            for (int in = 0; in < 4; in++) {
                int nn = nbase + tx * 4 + in;
                if (MODE == 0) {
                    float val = acc[im][in] + bias[nn];
                    if (nn < 512) g_h[(size_t)s * 512 + nn] = val;
                    else          g_c[(size_t)s * 512 + nn - 512] = val;
                } else {
                    float val = acc[im][in];
                    if (nn < NCOMP) g_pl[(size_t)s * NCOMP + nn] = val;
                    else            g_pr[(size_t)s * NCOMP + nn - NCOMP] = val;
                }
            }
        }
    }
}

// ---------------- step GEMM: partials of merged elements -----------------
// rows 0..nact-1 (length-sorted prefix); BM=32, BN=64, one wave guaranteed
__global__ __launch_bounds__(256)
void k_sgemm(const float* __restrict__ W, int step) {
    int nt = g_nact[step];
    int mbase = blockIdx.y * 32;
    if (mbase >= nt) return;
    int nbase = blockIdx.x * 64;
    __shared__ float As[16][32 + 4];
    __shared__ float Bs[16][64 + 4];
    int tid = threadIdx.x;
    int tx = tid & 15, ty = tid >> 4;

    // A loads: threads 0..127, one float4 each (32 rows x 16 K)
    int ar = tid >> 2, ak = (tid & 3) * 4;
    int m = mbase + ar;
    bool av = (tid < 128) && (m < nt);
    const float* aptr = av ? (g_h + (size_t)g_emerge[g_perm[m]] * 512) : g_h;
    // B loads: all 256 threads
    int br = tid >> 2, bk = (tid & 3) * 4;
    int nb = nbase + br;
    const float* wp = (nb < NCOMP) ? (W + (size_t)nb * 1024)
                                   : (W + (size_t)(nb - NCOMP) * 1024 + 512);
    float acc[2][4];
#pragma unroll
    for (int i = 0; i < 2; i++)
#pragma unroll
        for (int j = 0; j < 4; j++) acc[i][j] = 0.f;

    for (int kt = 0; kt < 512; kt += 16) {
        if (tid < 128) {
            float4 a = av ? *(const float4*)(aptr + kt + ak)
                          : make_float4(0.f, 0.f, 0.f, 0.f);
            As[ak + 0][ar] = a.x; As[ak + 1][ar] = a.y;
            As[ak + 2][ar] = a.z; As[ak + 3][ar] = a.w;
        }
        float4 bv = *(const float4*)(wp + kt + bk);
        Bs[bk + 0][br] = bv.x; Bs[bk + 1][br] = bv.y;
        Bs[bk + 2][br] = bv.z; Bs[bk + 3][br] = bv.w;
        __syncthreads();
#pragma unroll
        for (int kk = 0; kk < 16; kk++) {
            float a0 = As[kk][ty * 2], a1 = As[kk][ty * 2 + 1];
            float4 t = *(const float4*)&Bs[kk][tx * 4];
            float bb[4] = {t.x, t.y, t.z, t.w};
#pragma unroll
            for (int in = 0; in < 4; in++) {
                acc[0][in] += a0 * bb[in];
                acc[1][in] += a1 * bb[in];
            }
        }
        __syncthreads();
    }
#pragma unroll
    for (int im = 0; im < 2; im++) {
        int mm = mbase + ty * 2 + im;
        if (mm < nt) {
            int slot = g_emerge[g_perm[mm]];
#pragma unroll
            for (int in = 0; in < 4; in++) {
                int nn = nbase + tx * 4 + in;
                if (nn < NCOMP) g_pl[(size_t)slot * NCOMP + nn] = acc[im][in];
                else            g_pr[(size_t)slot * NCOMP + nn - NCOMP] = acc[im][in];
            }
        }
    }
}

// ---------------- initial pair elementwise (compacted list) --------------
__global__ void k_ew(const float* __restrict__ bc, const float* __restrict__ q) {
    int t = blockIdx.x;
    if (t >= g_pc[0]) return;
    int4 tk = g_pt[t];
    int b = tk.x, sl = tk.y, sr = tk.z, dst = tk.w;
    int e = threadIdx.x;
    const float4* pl  = (const float4*)(g_pl + (size_t)(b * 32 + sl) * NCOMP);
    const float4* pr  = (const float4*)(g_pr + (size_t)(b * 32 + sr) * NCOMP);
    const float4* bc4 = (const float4*)bc;
    const float4* cl4 = (const float4*)(g_c + (size_t)(b * 32 + sl) * H_);
    const float4* cr4 = (const float4*)(g_c + (size_t)(b * 32 + sr) * H_);
    float4* nh4 = (float4*)(g_nh + (size_t)(b * 32 + dst) * H_);
    float4* nc4 = (float4*)(g_nc + (size_t)(b * 32 + dst) * H_);
    const float4* q4 = (const float4*)q;

    float4 vi, vfl, vfr, vu, vo;
#define G(dst_, g_) { float4 a = pl[(g_)*128 + e]; float4 bq = pr[(g_)*128 + e]; float4 c = bc4[(g_)*128 + e]; \
    dst_.x = a.x + bq.x + c.x; dst_.y = a.y + bq.y + c.y; dst_.z = a.z + bq.z + c.z; dst_.w = a.w + bq.w + c.w; }
    G(vi, 0) G(vfl, 1) G(vfr, 2) G(vu, 3) G(vo, 4)
#undef G
    float4 cl = cl4[e], cr = cr4[e];
    float4 cn, hn;
#define C1(m) cn.m = cl.m * sigmf(vfl.m + 1.f) + cr.m * sigmf(vfr.m + 1.f) + tanhf(vu.m) * sigmf(vi.m); \
              hn.m = sigmf(vo.m) * tanhf(cn.m);
    C1(x) C1(y) C1(z) C1(w)
#undef C1
    nh4[e] = hn; nc4[e] = cn;
    float4 qv = q4[e];
    float accq = qv.x * hn.x + qv.y * hn.y + qv.z * hn.z + qv.w * hn.w;
    for (int o = 16; o > 0; o >>= 1) accq += __shfl_down_sync(0xffffffffu, accq, o);
    __shared__ float red[4];
    if ((threadIdx.x & 31) == 0) red[threadIdx.x >> 5] = accq;
    __syncthreads();
    if (threadIdx.x == 0) {
        float s = red[0] + red[1] + red[2] + red[3];
        g_logit[b * 32 + dst] = s * 0.04419417382415922f;
    }
}

// ---------------- fused: ew(step-1 tasks) + select(step) + commit --------
__global__ void k_fused(const int* __restrict__ length,
                        const float* __restrict__ bc, const float* __restrict__ q,
                        int step) {
    int b = blockIdx.x, tid = threadIdx.x;
    __shared__ float redc[2][4];
    __shared__ int s_sl;

    if (step > 0) {
        int ntask = g_ptn[b];
        int sub = tid >> 7, lt = tid & 127;
        int wig = (tid >> 5) & 3;
        bool valid = (sub < ntask);
        float accq = 0.f;
        int bdst = 0;
        if (valid) {
            int4 tk = g_ptask[b * 2 + sub];
            int sl = tk.y, sr = tk.z, dst = tk.w;
            bdst = b * 32 + dst;
            const float4* pl  = (const float4*)(g_pl + (size_t)(b * 32 + sl) * NCOMP);
            const float4* pr  = (const float4*)(g_pr + (size_t)(b * 32 + sr) * NCOMP);
            const float4* bc4 = (const float4*)bc;
            const float4* cl4 = (const float4*)(g_c + (size_t)(b * 32 + sl) * H_);
            const float4* cr4 = (const float4*)(g_c + (size_t)(b * 32 + sr) * H_);
            float4* nh4 = (float4*)(g_nh + (size_t)bdst * H_);
            float4* nc4 = (float4*)(g_nc + (size_t)bdst * H_);
            const float4* q4 = (const float4*)q;
            float4 vi, vfl, vfr, vu, vo;
#define G(dst_, g_) { float4 a = pl[(g_)*128 + lt]; float4 bq = pr[(g_)*128 + lt]; float4 c = bc4[(g_)*128 + lt]; \
    dst_.x = a.x + bq.x + c.x; dst_.y = a.y + bq.y + c.y; dst_.z = a.z + bq.z + c.z; dst_.w = a.w + bq.w + c.w; }
            G(vi, 0) G(vfl, 1) G(vfr, 2) G(vu, 3) G(vo, 4)
#undef G
            float4 cl = cl4[lt], cr = cr4[lt];
            float4 cn, hn;
#define C1(m) cn.m = cl.m * sigmf(vfl.m + 1.f) + cr.m * sigmf(vfr.m + 1.f) + tanhf(vu.m) * sigmf(vi.m); \
              hn.m = sigmf(vo.m) * tanhf(cn.m);
            C1(x) C1(y) C1(z) C1(w)
#undef C1
            nh4[lt] = hn; nc4[lt] = cn;
            float4 qv = q4[lt];
            accq = qv.x * hn.x + qv.y * hn.y + qv.z * hn.z + qv.w * hn.w;
        }
        for (int o = 16; o > 0; o >>= 1) accq += __shfl_down_sync(0xffffffffu, accq, o);
        if ((tid & 31) == 0) redc[sub][wig] = accq;
        __syncthreads();
        if (valid && lt == 0) {
            float s = redc[sub][0] + redc[sub][1] + redc[sub][2] + redc[sub][3];
            g_logit[bdst] = s * 0.04419417382415922f;
        }
        __syncthreads();
    }

    // select: parallel warp argmax (first-max tie-break == jnp.argmax)
    if (tid < 32) {
        int len = length[b];
        int vc = len - step - 1;
        int sl = -1, nt2 = 0;
        int* ip = g_idx + b * 32;
        if (vc >= 1) {
            float val = -3.0e38f;
            int ki = tid;
            if (tid < vc) val = g_logit[b * 32 + ip[tid]];
            for (int o = 16; o > 0; o >>= 1) {
                float ov = __shfl_down_sync(0xffffffffu, val, o);
                int   ok = __shfl_down_sync(0xffffffffu, ki, o);
                if (ov > val || (ov == val && ok < ki)) { val = ov; ki = ok; }
            }
            int jb = __shfl_sync(0xffffffffu, ki, 0);
            if (tid == 0) {
                sl = ip[jb];
                if (step < 30) {
                    if (jb >= 1)      g_ptask[b * 2 + nt2++] = make_int4(b, ip[jb - 1], sl, ip[jb - 1]);
                    if (jb <= vc - 2) g_ptask[b * 2 + nt2++] = make_int4(b, sl, ip[jb + 2], sl);
                }
                int n = 32 - step;
                for (int k2 = jb + 1; k2 < n - 1; k2++) ip[k2] = ip[k2 + 1];
            }
        }
        if (tid == 0) {
            g_ptn[b] = nt2;
            g_emerge[b] = (sl >= 0 && step < 30) ? (b * 32 + sl) : -1;
            s_sl = sl;
        }
    }
    __syncthreads();
    int sl = s_sl;
    if (sl >= 0) {   // commit merge: cached compose -> live h/c
        size_t ro = (size_t)(b * 32 + sl) * H_;
        int e = tid & 127;
        if (tid < 128) ((float4*)(g_h + ro))[e] = ((const float4*)(g_nh + ro))[e];
        else           ((float4*)(g_c + ro))[e] = ((const float4*)(g_nc + ro))[e];
    }
}

__global__ void k_final(float* __restrict__ out) {
    int b = blockIdx.x;   // element 0 lives in slot 0 forever
    ((float4*)out)[b * 128 + threadIdx.x] =
        ((const float4*)(g_h + (size_t)b * 32 * H_))[threadIdx.x];
}

// ---------------- launch ----------------
extern "C" void kernel_launch(void* const* d_in, const int* in_sizes, int n_in,
                              void* d_out, int out_size) {
    const float* x      = (const float*)d_in[0];
    const int*   length = (const int*)  d_in[1];
    const float* Ww     = (const float*)d_in[2];
    const float* bw     = (const float*)d_in[3];
    const float* Wc     = (const float*)d_in[4];
    const float* bc     = (const float*)d_in[5];
    const float* q      = (const float*)d_in[6];
    float* out = (float*)d_out;

    k_zero<<<1, 32>>>();
    k_init<<<B_, 32>>>(length);
    k_init2<<<1, 256>>>(length);

    // word projection (gathered, valid elements only): h|c = x @ Ww^T + bw
    k_ggemm<0><<<dim3(1024 / 64, 64), 256>>>(x, Ww, bw);
    // initial partial fill: pl|pr = Wl@h | Wr@h for all valid elements
    k_ggemm<1><<<dim3(5120 / 64, 64), 256>>>((const float*)0, Wc, (const float*)0);
    // initial pair cache (adds + activations + logits)
    k_ew<<<8192, 128>>>(bc, q);

    for (int i = 0; i < 31; i++) {
        k_fused<<<B_, 256>>>(length, bc, q, i);
        if (i < 30)
            k_sgemm<<<dim3(5120 / 64, 8), 256>>>(Wc, i);
    }
    k_final<<<B_, 128>>>(out);
}

// round 9
// speedup vs baseline: 2.0541x; 1.1863x over previous
#include <cuda_runtime.h>
#include <math.h>

// Shapes (fixed by problem)
#define B_    256
#define L_    32
#define H_    512
#define NROWS (B_ * L_)      // 8192 slots
#define NCOMP (5 * H_)       // 2560

// ---------------- persistent device state (device-code access ONLY) ------
__device__ float g_h [NROWS * H_];
__device__ float g_c [NROWS * H_];
__device__ float g_nh[NROWS * H_];
__device__ float g_nc[NROWS * H_];
__device__ float g_pl[NROWS * NCOMP];
__device__ float g_pr[NROWS * NCOMP];
__device__ float g_logit[NROWS];
__device__ int   g_idx[B_ * L_];
__device__ int   g_et[NROWS];            // initial element-task list (compacted)
__device__ int4  g_pt[NROWS];            // initial pair-task list (compacted)
__device__ int   g_ec[2];
__device__ int   g_pc[2];
__device__ int   g_perm[B_];             // batches sorted by length desc (stable)
__device__ int   g_nact[32];             // #batches merging at step i
__device__ int   g_emerge[B_];           // per-batch merged slot this step (-1 none)
__device__ int   g_ptn[B_];              // per-batch pair-task count (<=2)
__device__ int4  g_ptask[B_ * 2];        // per-batch pair tasks

__device__ __forceinline__ float sigmf(float x) { return 1.f / (1.f + expf(-x)); }

// ---------------- init ----------------
__global__ void k_zero() {
    if (threadIdx.x < 2) { g_ec[threadIdx.x] = 0; g_pc[threadIdx.x] = 0; }
}

__global__ void k_init(const int* __restrict__ length) {
    int b = blockIdx.x;
    g_idx[b * 32 + threadIdx.x] = threadIdx.x;
    if (threadIdx.x == 0) {
        int len = length[b];
        int be = atomicAdd(&g_ec[0], len);
        for (int e = 0; e < len; e++) g_et[be + e] = b * 32 + e;
        int bp = atomicAdd(&g_pc[0], len - 1);
        for (int k = 0; k < len - 1; k++) g_pt[bp + k] = make_int4(b, k, k + 1, k);
    }
}

// length-sorted permutation + per-step active count
__global__ void k_init2(const int* __restrict__ length) {
    __shared__ int slen[B_];
    int t = threadIdx.x;
    slen[t] = length[t];
    __syncthreads();
    int myl = slen[t];
    int rank = 0;
    for (int j = 0; j < B_; j++) {
        int lj = slen[j];
        if (lj > myl || (lj == myl && j < t)) rank++;
    }
    g_perm[rank] = t;
    if (t < 31) {            // batch merges at step i iff len >= i+2
        int cnt = 0;
        for (int j = 0; j < B_; j++) if (slen[j] >= t + 2) cnt++;
        g_nact[t] = cnt;
    }
}

// ---------------- initial gather GEMMs, double-buffered ------------------
// MODE 0 (word proj): A = X[et], B = Ww (N=1024), +bw -> g_h|g_c
// MODE 1 (fill partials): A = g_h[et], B = Wc halves (N=5120) -> g_pl|g_pr
template<int MODE>
__global__ void k_ggemm(const float* __restrict__ X,
                        const float* __restrict__ W,
                        const float* __restrict__ bias)
{
    constexpr int BM = 128, BN = 64, BK = 16;
    int nt = g_ec[0];
    int mbase = blockIdx.y * BM;
    if (mbase >= nt) return;
    int nbase = blockIdx.x * BN;
    __shared__ float As[2][BK][BM + 4];
    __shared__ float Bs[2][BK][BN + 4];
    int tid = threadIdx.x;
    int tx = tid & 15, ty = tid >> 4;
    float acc[8][4];
#pragma unroll
    for (int i = 0; i < 8; i++)
#pragma unroll
        for (int j = 0; j < 4; j++) acc[i][j] = 0.f;

    const float* Abase = (MODE == 0) ? X : g_h;
    const float* aptr[2];
    int ar[2], ak[2];
    bool av[2];
#pragma unroll
    for (int l = 0; l < 2; l++) {
        int fa = tid + l * 256;
        ar[l] = fa >> 2; ak[l] = (fa & 3) * 4;
        int m = mbase + ar[l];
        av[l] = (m < nt);
        aptr[l] = av[l] ? (Abase + (size_t)g_et[m] * 512) : Abase;
    }
    int br = tid >> 2, bk = (tid & 3) * 4;
    int nb = nbase + br;
    const float* wp;
    if (MODE == 0) wp = W + (size_t)nb * 512;
    else           wp = (nb < NCOMP) ? (W + (size_t)nb * 1024)
                                     : (W + (size_t)(nb - NCOMP) * 1024 + 512);

    float4 pa0, pa1, pb;
    pa0 = av[0] ? *(const float4*)(aptr[0] + ak[0]) : make_float4(0.f,0.f,0.f,0.f);
    pa1 = av[1] ? *(const float4*)(aptr[1] + ak[1]) : make_float4(0.f,0.f,0.f,0.f);
    pb  = *(const float4*)(wp + bk);
    As[0][ak[0] + 0][ar[0]] = pa0.x; As[0][ak[0] + 1][ar[0]] = pa0.y;
    As[0][ak[0] + 2][ar[0]] = pa0.z; As[0][ak[0] + 3][ar[0]] = pa0.w;
    As[0][ak[1] + 0][ar[1]] = pa1.x; As[0][ak[1] + 1][ar[1]] = pa1.y;
    As[0][ak[1] + 2][ar[1]] = pa1.z; As[0][ak[1] + 3][ar[1]] = pa1.w;
    Bs[0][bk + 0][br] = pb.x; Bs[0][bk + 1][br] = pb.y;
    Bs[0][bk + 2][br] = pb.z; Bs[0][bk + 3][br] = pb.w;
    __syncthreads();

    constexpr int NIT = 512 / BK;
    for (int it = 0; it < NIT; it++) {
        int cur = it & 1;
        if (it + 1 < NIT) {            // prefetch next chunk into regs
            int kt = (it + 1) * BK;
            pa0 = av[0] ? *(const float4*)(aptr[0] + kt + ak[0]) : make_float4(0.f,0.f,0.f,0.f);
            pa1 = av[1] ? *(const float4*)(aptr[1] + kt + ak[1]) : make_float4(0.f,0.f,0.f,0.f);
            pb  = *(const float4*)(wp + kt + bk);
        }
#pragma unroll
        for (int kk = 0; kk < BK; kk++) {
            float a[8], bb[4];
            {
                float4 t0 = *(const float4*)&As[cur][kk][ty * 8];
                float4 t1 = *(const float4*)&As[cur][kk][ty * 8 + 4];
                a[0] = t0.x; a[1] = t0.y; a[2] = t0.z; a[3] = t0.w;
                a[4] = t1.x; a[5] = t1.y; a[6] = t1.z; a[7] = t1.w;
            }
            {
                float4 t = *(const float4*)&Bs[cur][kk][tx * 4];
                bb[0] = t.x; bb[1] = t.y; bb[2] = t.z; bb[3] = t.w;
            }
#pragma unroll
            for (int im = 0; im < 8; im++)
#pragma unroll
                for (int in = 0; in < 4; in++) acc[im][in] += a[im] * bb[in];
        }
        if (it + 1 < NIT) {
            int nxt = 1 - cur;
            As[nxt][ak[0] + 0][ar[0]] = pa0.x; As[nxt][ak[0] + 1][ar[0]] = pa0.y;
            As[nxt][ak[0] + 2][ar[0]] = pa0.z; As[nxt][ak[0] + 3][ar[0]] = pa0.w;
            As[nxt][ak[1] + 0][ar[1]] = pa1.x; As[nxt][ak[1] + 1][ar[1]] = pa1.y;
            As[nxt][ak[1] + 2][ar[1]] = pa1.z; As[nxt][ak[1] + 3][ar[1]] = pa1.w;
            Bs[nxt][bk + 0][br] = pb.x; Bs[nxt][bk + 1][br] = pb.y;
            Bs[nxt][bk + 2][br] = pb.z; Bs[nxt][bk + 3][br] = pb.w;
            __syncthreads();
        }
    }
#pragma unroll
    for (int im = 0; im < 8; im++) {
        int m = mbase + ty * 8 + im;
        if (m < nt) {
            int s = g_et[m];
#pragma unroll
            for (int in = 0; in < 4; in++) {
                int nn = nbase + tx * 4 + in;
                if (MODE == 0) {
                    float val = acc[im][in] + bias[nn];
                    if (nn < 512) g_h[(size_t)s * 512 + nn] = val;
                    else          g_c[(size_t)s * 512 + nn - 512] = val;
                } else {
                    float val = acc[im][in];
                    if (nn < NCOMP) g_pl[(size_t)s * NCOMP + nn] = val;
                    else            g_pr[(size_t)s * NCOMP + nn - NCOMP] = val;
                }
            }
        }
    }
}

// ---------------- step GEMM: partials of merged elements -----------------
// rows 0..nact-1 (length-sorted prefix); BM=64, BN=64, 4x4/thread, dbuf
__global__ __launch_bounds__(256)
void k_sgemm(const float* __restrict__ W, int step) {
    constexpr int BK = 16;
    int nt = g_nact[step];
    int mbase = blockIdx.y * 64;
    if (mbase >= nt) return;
    int nbase = blockIdx.x * 64;
    __shared__ float As[2][BK][64 + 4];
    __shared__ float Bs[2][BK][64 + 4];
    int tid = threadIdx.x;
    int tx = tid & 15, ty = tid >> 4;

    int ar = tid >> 2, ak = (tid & 3) * 4;
    int m = mbase + ar;
    bool av = (m < nt);
    const float* aptr = av ? (g_h + (size_t)g_emerge[g_perm[m]] * 512) : g_h;
    int br = tid >> 2, bk = (tid & 3) * 4;
    int nb = nbase + br;
    const float* wp = (nb < NCOMP) ? (W + (size_t)nb * 1024)
                                   : (W + (size_t)(nb - NCOMP) * 1024 + 512);
    float acc[4][4];
#pragma unroll
    for (int i = 0; i < 4; i++)
#pragma unroll
        for (int j = 0; j < 4; j++) acc[i][j] = 0.f;

    float4 pa, pb;
    pa = av ? *(const float4*)(aptr + ak) : make_float4(0.f,0.f,0.f,0.f);
    pb = *(const float4*)(wp + bk);
    As[0][ak + 0][ar] = pa.x; As[0][ak + 1][ar] = pa.y;
    As[0][ak + 2][ar] = pa.z; As[0][ak + 3][ar] = pa.w;
    Bs[0][bk + 0][br] = pb.x; Bs[0][bk + 1][br] = pb.y;
    Bs[0][bk + 2][br] = pb.z; Bs[0][bk + 3][br] = pb.w;
    __syncthreads();

    constexpr int NIT = 512 / BK;
    for (int it = 0; it < NIT; it++) {
        int cur = it & 1;
        if (it + 1 < NIT) {
            int kt = (it + 1) * BK;
            pa = av ? *(const float4*)(aptr + kt + ak) : make_float4(0.f,0.f,0.f,0.f);
            pb = *(const float4*)(wp + kt + bk);
        }
#pragma unroll
        for (int kk = 0; kk < BK; kk++) {
            float4 t0 = *(const float4*)&As[cur][kk][ty * 4];
            float4 t1 = *(const float4*)&Bs[cur][kk][tx * 4];
            float a[4] = {t0.x, t0.y, t0.z, t0.w};
            float bb[4] = {t1.x, t1.y, t1.z, t1.w};
#pragma unroll
            for (int im = 0; im < 4; im++)
#pragma unroll
                for (int in = 0; in < 4; in++) acc[im][in] += a[im] * bb[in];
        }
        if (it + 1 < NIT) {
            int nxt = 1 - cur;
            As[nxt][ak + 0][ar] = pa.x; As[nxt][ak + 1][ar] = pa.y;
            As[nxt][ak + 2][ar] = pa.z; As[nxt][ak + 3][ar] = pa.w;
            Bs[nxt][bk + 0][br] = pb.x; Bs[nxt][bk + 1][br] = pb.y;
            Bs[nxt][bk + 2][br] = pb.z; Bs[nxt][bk + 3][br] = pb.w;
            __syncthreads();
        }
    }
#pragma unroll
    for (int im = 0; im < 4; im++) {
        int mm = mbase + ty * 4 + im;
        if (mm < nt) {
            int slot = g_emerge[g_perm[mm]];
#pragma unroll
            for (int in = 0; in < 4; in++) {
                int nn = nbase + tx * 4 + in;
                if (nn < NCOMP) g_pl[(size_t)slot * NCOMP + nn] = acc[im][in];
                else            g_pr[(size_t)slot * NCOMP + nn - NCOMP] = acc[im][in];
            }
        }
    }
}

// ---------------- initial pair elementwise (compacted list) --------------
__global__ void k_ew(const float* __restrict__ bc, const float* __restrict__ q) {
    int t = blockIdx.x;
    if (t >= g_pc[0]) return;
    int4 tk = g_pt[t];
    int b = tk.x, sl = tk.y, sr = tk.z, dst = tk.w;
    int e = threadIdx.x;
    const float4* pl  = (const float4*)(g_pl + (size_t)(b * 32 + sl) * NCOMP);
    const float4* pr  = (const float4*)(g_pr + (size_t)(b * 32 + sr) * NCOMP);
    const float4* bc4 = (const float4*)bc;
    const float4* cl4 = (const float4*)(g_c + (size_t)(b * 32 + sl) * H_);
    const float4* cr4 = (const float4*)(g_c + (size_t)(b * 32 + sr) * H_);
    float4* nh4 = (float4*)(g_nh + (size_t)(b * 32 + dst) * H_);
    float4* nc4 = (float4*)(g_nc + (size_t)(b * 32 + dst) * H_);
    const float4* q4 = (const float4*)q;

    float4 vi, vfl, vfr, vu, vo;
#define G(dst_, g_) { float4 a = pl[(g_)*128 + e]; float4 bq = pr[(g_)*128 + e]; float4 c = bc4[(g_)*128 + e]; \
    dst_.x = a.x + bq.x + c.x; dst_.y = a.y + bq.y + c.y; dst_.z = a.z + bq.z + c.z; dst_.w = a.w + bq.w + c.w; }
    G(vi, 0) G(vfl, 1) G(vfr, 2) G(vu, 3) G(vo, 4)
#undef G
    float4 cl = cl4[e], cr = cr4[e];
    float4 cn, hn;
#define C1(m) cn.m = cl.m * sigmf(vfl.m + 1.f) + cr.m * sigmf(vfr.m + 1.f) + tanhf(vu.m) * sigmf(vi.m); \
              hn.m = sigmf(vo.m) * tanhf(cn.m);
    C1(x) C1(y) C1(z) C1(w)
#undef C1
    nh4[e] = hn; nc4[e] = cn;
    float4 qv = q4[e];
    float accq = qv.x * hn.x + qv.y * hn.y + qv.z * hn.z + qv.w * hn.w;
    for (int o = 16; o > 0; o >>= 1) accq += __shfl_down_sync(0xffffffffu, accq, o);
    __shared__ float red[4];
    if ((threadIdx.x & 31) == 0) red[threadIdx.x >> 5] = accq;
    __syncthreads();
    if (threadIdx.x == 0) {
        float s = red[0] + red[1] + red[2] + red[3];
        g_logit[b * 32 + dst] = s * 0.04419417382415922f;
    }
}

// ---------------- fused: ew(step-1 tasks) + select(step) + commit --------
__global__ void k_fused(const int* __restrict__ length,
                        const float* __restrict__ bc, const float* __restrict__ q,
                        int step) {
    int b = blockIdx.x, tid = threadIdx.x;
    __shared__ float redc[2][4];
    __shared__ int s_sl;

    if (step > 0) {
        int ntask = g_ptn[b];
        int sub = tid >> 7, lt = tid & 127;
        int wig = (tid >> 5) & 3;
        bool valid = (sub < ntask);
        float accq = 0.f;
        int bdst = 0;
        if (valid) {
            int4 tk = g_ptask[b * 2 + sub];
            int sl = tk.y, sr = tk.z, dst = tk.w;
            bdst = b * 32 + dst;
            const float4* pl  = (const float4*)(g_pl + (size_t)(b * 32 + sl) * NCOMP);
            const float4* pr  = (const float4*)(g_pr + (size_t)(b * 32 + sr) * NCOMP);
            const float4* bc4 = (const float4*)bc;
            const float4* cl4 = (const float4*)(g_c + (size_t)(b * 32 + sl) * H_);
            const float4* cr4 = (const float4*)(g_c + (size_t)(b * 32 + sr) * H_);
            float4* nh4 = (float4*)(g_nh + (size_t)bdst * H_);
            float4* nc4 = (float4*)(g_nc + (size_t)bdst * H_);
            const float4* q4 = (const float4*)q;
            float4 vi, vfl, vfr, vu, vo;
#define G(dst_, g_) { float4 a = pl[(g_)*128 + lt]; float4 bq = pr[(g_)*128 + lt]; float4 c = bc4[(g_)*128 + lt]; \
    dst_.x = a.x + bq.x + c.x; dst_.y = a.y + bq.y + c.y; dst_.z = a.z + bq.z + c.z; dst_.w = a.w + bq.w + c.w; }
            G(vi, 0) G(vfl, 1) G(vfr, 2) G(vu, 3) G(vo, 4)
#undef G
            float4 cl = cl4[lt], cr = cr4[lt];
            float4 cn, hn;
#define C1(m) cn.m = cl.m * sigmf(vfl.m + 1.f) + cr.m * sigmf(vfr.m + 1.f) + tanhf(vu.m) * sigmf(vi.m); \
              hn.m = sigmf(vo.m) * tanhf(cn.m);
            C1(x) C1(y) C1(z) C1(w)
#undef C1
            nh4[lt] = hn; nc4[lt] = cn;
            float4 qv = q4[lt];
            accq = qv.x * hn.x + qv.y * hn.y + qv.z * hn.z + qv.w * hn.w;
        }
        for (int o = 16; o > 0; o >>= 1) accq += __shfl_down_sync(0xffffffffu, accq, o);
        if ((tid & 31) == 0) redc[sub][wig] = accq;
        __syncthreads();
        if (valid && lt == 0) {
            float s = redc[sub][0] + redc[sub][1] + redc[sub][2] + redc[sub][3];
            g_logit[bdst] = s * 0.04419417382415922f;
        }
        __syncthreads();
    }

    // select: parallel warp argmax (first-max tie-break == jnp.argmax)
    if (tid < 32) {
        int len = length[b];
        int vc = len - step - 1;
        int sl = -1, nt2 = 0;
        int* ip = g_idx + b * 32;
        if (vc >= 1) {
            float val = -3.0e38f;
            int ki = tid;
            if (tid < vc) val = g_logit[b * 32 + ip[tid]];
            for (int o = 16; o > 0; o >>= 1) {
                float ov = __shfl_down_sync(0xffffffffu, val, o);
                int   ok = __shfl_down_sync(0xffffffffu, ki, o);
                if (ov > val || (ov == val && ok < ki)) { val = ov; ki = ok; }
            }
            int jb = __shfl_sync(0xffffffffu, ki, 0);
            if (tid == 0) {
                sl = ip[jb];
                if (step < 30) {
                    if (jb >= 1)      g_ptask[b * 2 + nt2++] = make_int4(b, ip[jb - 1], sl, ip[jb - 1]);
                    if (jb <= vc - 2) g_ptask[b * 2 + nt2++] = make_int4(b, sl, ip[jb + 2], sl);
                }
                int n = 32 - step;
                for (int k2 = jb + 1; k2 < n - 1; k2++) ip[k2] = ip[k2 + 1];
            }
        }
        if (tid == 0) {
            g_ptn[b] = nt2;
            g_emerge[b] = (sl >= 0 && step < 30) ? (b * 32 + sl) : -1;
            s_sl = sl;
        }
    }
    __syncthreads();
    int sl = s_sl;
    if (sl >= 0) {   // commit merge: cached compose -> live h/c
        size_t ro = (size_t)(b * 32 + sl) * H_;
        int e = tid & 127;
        if (tid < 128) ((float4*)(g_h + ro))[e] = ((const float4*)(g_nh + ro))[e];
        else           ((float4*)(g_c + ro))[e] = ((const float4*)(g_nc + ro))[e];
    }
}

__global__ void k_final(float* __restrict__ out) {
    int b = blockIdx.x;   // element 0 lives in slot 0 forever
    ((float4*)out)[b * 128 + threadIdx.x] =
        ((const float4*)(g_h + (size_t)b * 32 * H_))[threadIdx.x];
}

// ---------------- launch ----------------
extern "C" void kernel_launch(void* const* d_in, const int* in_sizes, int n_in,
                              void* d_out, int out_size) {
    const float* x      = (const float*)d_in[0];
    const int*   length = (const int*)  d_in[1];
    const float* Ww     = (const float*)d_in[2];
    const float* bw     = (const float*)d_in[3];
    const float* Wc     = (const float*)d_in[4];
    const float* bc     = (const float*)d_in[5];
    const float* q      = (const float*)d_in[6];
    float* out = (float*)d_out;

    k_zero<<<1, 32>>>();
    k_init<<<B_, 32>>>(length);
    k_init2<<<1, 256>>>(length);

    // word projection (gathered, valid elements only): h|c = x @ Ww^T + bw
    k_ggemm<0><<<dim3(1024 / 64, 64), 256>>>(x, Ww, bw);
    // initial partial fill: pl|pr = Wl@h | Wr@h for all valid elements
    k_ggemm<1><<<dim3(5120 / 64, 64), 256>>>((const float*)0, Wc, (const float*)0);
    // initial pair cache (adds + activations + logits)
    k_ew<<<8192, 128>>>(bc, q);

    for (int i = 0; i < 31; i++) {
        k_fused<<<B_, 256>>>(length, bc, q, i);
        if (i < 30)
            k_sgemm<<<dim3(5120 / 64, 4), 256>>>(Wc, i);
    }
    k_final<<<B_, 128>>>(out);
}